// round 4
// baseline (speedup 1.0000x reference)
#include <cuda_runtime.h>
#include <cuda_bf16.h>

#define N_NODES 100000
#define N_EDGES 3200000
#define HID 16

// ---------------- device scratch ----------------
__device__ float g_aggs[N_NODES];    // layer-1 scalar segment sum
__device__ float g_alpha[N_NODES];   // z . (proc_w_rel @ dec_w_rel)
__device__ float g_bg[N_NODES];      // beta + gamma + c1
__device__ float g_dc[N_NODES];      // delta + c2 + dec_b
__device__ float g_A[N_NODES];       // segment_sum(alpha)
__device__ float g_tg[N_NODES];      // A + bg  (scatter source, pass 3)
__device__ float g_T[N_NODES];       // final scalar segment sum
__device__ __align__(16) int2 g_edge[N_EDGES];  // packed {src, dst}
__device__ int   g_is64;
__device__ float g_w1[HID], g_w2[HID], g_w3[HID], g_w4[HID];
__device__ float g_c1, g_c2;

// ---------------- kernels ----------------

__global__ void k_init() {
    int i = blockIdx.x * blockDim.x + threadIdx.x;
    if (i < N_NODES) { g_aggs[i] = 0.f; g_A[i] = 0.f; g_T[i] = 0.f; }
}

// int64 vs int32 edge_index detection (node ids < 1e5 << 2^32).
__global__ void k_detect(const void* ei) {
    const unsigned long long* p = (const unsigned long long*)ei;
    int bad = 0;
    for (int i = threadIdx.x; i < 256; i += blockDim.x)
        if ((p[i] >> 32) != 0ull) bad = 1;
    bad = __syncthreads_or(bad);
    if (threadIdx.x == 0) g_is64 = bad ? 0 : 1;
}

// Fold proc/dec weights:
//   w1 = proc_w_rel @ dec_w_rel    w2 = proc_w_rel @ dec_w_root
//   w3 = proc_w_root @ dec_w_rel   w4 = proc_w_root @ dec_w_root
//   c1 = proc_b . dec_w_rel        c2 = proc_b . dec_w_root
__global__ void k_foldw(const float* __restrict__ proc_w_rel,
                        const float* __restrict__ proc_w_root,
                        const float* __restrict__ proc_b,
                        const float* __restrict__ dec_w_rel,
                        const float* __restrict__ dec_w_root) {
    int t = threadIdx.x;            // 64 threads
    int g = t & 15;
    int which = t >> 4;
    const float* M = (which < 2) ? proc_w_rel : proc_w_root;
    const float* v = (which & 1) ? dec_w_root : dec_w_rel;
    float acc = 0.f;
#pragma unroll
    for (int f = 0; f < HID; f++) acc = fmaf(M[g * HID + f], v[f], acc);
    if (which == 0) g_w1[g] = acc;
    else if (which == 1) g_w2[g] = acc;
    else if (which == 2) g_w3[g] = acc;
    else g_w4[g] = acc;
    if (t == 0) {
        float a = 0.f, b = 0.f;
#pragma unroll
        for (int f = 0; f < HID; f++) {
            a = fmaf(proc_b[f], dec_w_rel[f], a);
            b = fmaf(proc_b[f], dec_w_root[f], b);
        }
        g_c1 = a; g_c2 = b;
    }
}

// Edge pass 1: convert edge list to packed int2 AND scatter x scalar.
// 2 edges per thread.
__global__ void k_convert_scatter1(const void* ei, const float* __restrict__ x) {
    int t = blockIdx.x * blockDim.x + threadIdx.x;
    int e = t * 2;
    if (e >= N_EDGES) return;
    int s0, d0, s1, d1;
    if (g_is64) {
        const longlong2* ps = (const longlong2*)ei;                 // src row
        const longlong2* pd = ps + (N_EDGES / 2);                   // dst row
        longlong2 sv = ps[t];
        longlong2 dv = pd[t];
        s0 = (int)sv.x; s1 = (int)sv.y;
        d0 = (int)dv.x; d1 = (int)dv.y;
    } else {
        const int2* ps = (const int2*)ei;
        const int2* pd = ps + (N_EDGES / 2);
        int2 sv = ps[t];
        int2 dv = pd[t];
        s0 = sv.x; s1 = sv.y;
        d0 = dv.x; d1 = dv.y;
    }
    *(int4*)&g_edge[e] = make_int4(s0, d0, s1, d1);
    float x0 = __ldg(&x[s0]);
    float x1 = __ldg(&x[s1]);
    atomicAdd(&g_aggs[d0], x0);
    atomicAdd(&g_aggs[d1], x1);
}

// Node pass 1: z = relu(enc), project onto folded directions.
__global__ void k_node1(const float* __restrict__ x,
                        const float* __restrict__ enc_w_rel,
                        const float* __restrict__ enc_w_root,
                        const float* __restrict__ enc_b,
                        const float* __restrict__ dec_b) {
    __shared__ float sWrel[HID], sWroot[HID], sB[HID];
    __shared__ float s1[HID], s2[HID], s3[HID], s4[HID];
    __shared__ float sc1, sc2, sDb;
    int t = threadIdx.x;
    if (t < HID) {
        sWrel[t] = enc_w_rel[t]; sWroot[t] = enc_w_root[t]; sB[t] = enc_b[t];
        s1[t] = g_w1[t]; s2[t] = g_w2[t]; s3[t] = g_w3[t]; s4[t] = g_w4[t];
    }
    if (t == 0) { sc1 = g_c1; sc2 = g_c2; sDb = dec_b[0]; }
    __syncthreads();

    int i = blockIdx.x * blockDim.x + t;
    if (i >= N_NODES) return;

    float a  = g_aggs[i];
    float xv = __ldg(&x[i]);
    float al = 0.f, ga = 0.f, be = 0.f, de = 0.f;
#pragma unroll
    for (int f = 0; f < HID; f++) {
        float z = fmaxf(fmaf(a, sWrel[f], fmaf(xv, sWroot[f], sB[f])), 0.f);
        al = fmaf(z, s1[f], al);
        ga = fmaf(z, s2[f], ga);
        be = fmaf(z, s3[f], be);
        de = fmaf(z, s4[f], de);
    }
    g_alpha[i] = al;
    g_bg[i]    = be + ga + sc1;
    g_dc[i]    = de + sc2 + sDb;
}

// Edge pass 2: A[dst] += alpha[src].  4 edges per thread.
__global__ void k_edge2() {
    int t = blockIdx.x * blockDim.x + threadIdx.x;
    int e = t * 4;
    if (e >= N_EDGES) return;
    int4 ab = *(const int4*)&g_edge[e];
    int4 cd = *(const int4*)&g_edge[e + 2];
    float v0 = __ldg(&g_alpha[ab.x]);
    float v1 = __ldg(&g_alpha[ab.z]);
    float v2 = __ldg(&g_alpha[cd.x]);
    float v3 = __ldg(&g_alpha[cd.z]);
    atomicAdd(&g_A[ab.y], v0);
    atomicAdd(&g_A[ab.w], v1);
    atomicAdd(&g_A[cd.y], v2);
    atomicAdd(&g_A[cd.w], v3);
}

// Node pass 2: tg = A + bg.
__global__ void k_node2() {
    int i = blockIdx.x * blockDim.x + threadIdx.x;
    if (i >= N_NODES) return;
    g_tg[i] = g_A[i] + g_bg[i];
}

// Edge pass 3: T[dst] += tg[src].  4 edges per thread.
__global__ void k_edge3() {
    int t = blockIdx.x * blockDim.x + threadIdx.x;
    int e = t * 4;
    if (e >= N_EDGES) return;
    int4 ab = *(const int4*)&g_edge[e];
    int4 cd = *(const int4*)&g_edge[e + 2];
    float v0 = __ldg(&g_tg[ab.x]);
    float v1 = __ldg(&g_tg[ab.z]);
    float v2 = __ldg(&g_tg[cd.x]);
    float v3 = __ldg(&g_tg[cd.z]);
    atomicAdd(&g_T[ab.y], v0);
    atomicAdd(&g_T[ab.w], v1);
    atomicAdd(&g_T[cd.y], v2);
    atomicAdd(&g_T[cd.w], v3);
}

// Node pass 3: out = relu(T + dc).
__global__ void k_node3(float* __restrict__ out) {
    int i = blockIdx.x * blockDim.x + threadIdx.x;
    if (i >= N_NODES) return;
    out[i] = fmaxf(g_T[i] + g_dc[i], 0.f);
}

// ---------------- launch ----------------
extern "C" void kernel_launch(void* const* d_in, const int* in_sizes, int n_in,
                              void* d_out, int out_size) {
    const float* x          = (const float*)d_in[0];
    const void*  ei         = d_in[1];
    const float* enc_w_rel  = (const float*)d_in[2];
    const float* enc_w_root = (const float*)d_in[3];
    const float* enc_b      = (const float*)d_in[4];
    const float* proc_w_rel = (const float*)d_in[5];
    const float* proc_w_root= (const float*)d_in[6];
    const float* proc_b     = (const float*)d_in[7];
    const float* dec_w_rel  = (const float*)d_in[8];
    const float* dec_w_root = (const float*)d_in[9];
    const float* dec_b      = (const float*)d_in[10];
    float* out = (float*)d_out;

    const int B = 256;
    const int GN  = (N_NODES + B - 1) / B;
    const int GE2 = (N_EDGES / 2 + B - 1) / B;   // 2 edges/thread
    const int GE4 = (N_EDGES / 4 + B - 1) / B;   // 4 edges/thread

    k_init<<<GN, B>>>();
    k_detect<<<1, 256>>>(ei);
    k_foldw<<<1, 64>>>(proc_w_rel, proc_w_root, proc_b, dec_w_rel, dec_w_root);
    k_convert_scatter1<<<GE2, B>>>(ei, x);
    k_node1<<<GN, B>>>(x, enc_w_rel, enc_w_root, enc_b, dec_b);
    k_edge2<<<GE4, B>>>();
    k_node2<<<GN, B>>>();
    k_edge3<<<GE4, B>>>();
    k_node3<<<GN, B>>>(out);
}